// round 7
// baseline (speedup 1.0000x reference)
#include <cuda_runtime.h>
#include <cstdint>
#include <cstddef>

#define Bn 4096
#define Tn 200
#define Tl 100          // rows per half-CTA
#define Dn 128
#define Hn 16
#define NTHREADS 256

// smem floats: sf 12800 | sB 2048 (aliased by spart8) | sq 128 | sc 16 | sw2 16
//              sscore 104 | sred 16 | scpart 256 = 15384 floats = 61536 B
#define SMEM_FLOATS (12800 + 2048 + 128 + 16 + 16 + 104 + 16 + 256)

__device__ float    g_part[Bn][Dn];
__device__ float    g_sum[Bn];
__device__ unsigned g_cnt[Bn];

__device__ __forceinline__ uint32_t f2tf32(float x) {
    uint32_t u;
    asm("cvt.rna.tf32.f32 %0, %1;" : "=r"(u) : "f"(x));
    return u;
}

__device__ __forceinline__ void mma_tf32(float c[4], const uint32_t a[4],
                                         uint32_t b0, uint32_t b1) {
    asm volatile(
        "mma.sync.aligned.m16n8k8.row.col.f32.tf32.tf32.f32 "
        "{%0,%1,%2,%3}, {%4,%5,%6,%7}, {%8,%9}, {%0,%1,%2,%3};"
        : "+f"(c[0]), "+f"(c[1]), "+f"(c[2]), "+f"(c[3])
        : "r"(a[0]), "r"(a[1]), "r"(a[2]), "r"(a[3]), "r"(b0), "r"(b1));
}

__global__ void __launch_bounds__(NTHREADS, 3) din_kernel(
    const float* __restrict__ query,
    const float* __restrict__ facts,
    const int* __restrict__ mask,
    const float* __restrict__ W1,
    const float* __restrict__ b1,
    const float* __restrict__ W2,
    const float* __restrict__ b2,
    float* __restrict__ out)
{
    extern __shared__ float smem[];
    float* sf     = smem;                 // swizzled 100x128 facts half-tile (50 KB)
    float* sB     = sf + Tl*Dn;           // packed tf32 B fragments; later spart8
    float* sq     = sB + 2048;            // 128
    float* sc     = sq + Dn;              // 16
    float* sw2    = sc + Hn;              // 16
    float* sscore = sw2 + Hn;             // 104 (exp(score), local t)
    float* sred   = sscore + 104;         // 16
    float* scpart = sred + 16;            // 256
    float* spart8 = sB;                   // alias: 8 x 128 weighted-sum partials

    const int b   = blockIdx.x >> 1;
    const int hb  = blockIdx.x & 1;       // which half of T
    const int tid = threadIdx.x;
    const float b2v = b2[0];

    // ---- load this half's 100x128 tile: group0 rows 0..63, group1 rows 64..99 ----
    {
        const float4* fg = (const float4*)(facts + (size_t)b * (Tn * Dn) + hb * (Tl * Dn));
        #pragma unroll
        for (int k = 0; k < 8; ++k) {        // 2048 f4
            int i  = tid + k * NTHREADS;
            int t  = i >> 5;
            int dg = i & 31;
            float4* dst = ((float4*)sf) + (t * 32 + (dg ^ (t & 31)));
            unsigned saddr = (unsigned)__cvta_generic_to_shared(dst);
            asm volatile("cp.async.cg.shared.global [%0], [%1], 16;\n"
                         :: "r"(saddr), "l"(fg + i) : "memory");
        }
        asm volatile("cp.async.commit_group;\n" ::: "memory");
        #pragma unroll
        for (int k = 0; k < 5; ++k) {        // 1152 f4
            int i = 2048 + tid + k * NTHREADS;
            if (i < Tl * 32) {
                int t  = i >> 5;
                int dg = i & 31;
                float4* dst = ((float4*)sf) + (t * 32 + (dg ^ (t & 31)));
                unsigned saddr = (unsigned)__cvta_generic_to_shared(dst);
                asm volatile("cp.async.cg.shared.global [%0], [%1], 16;\n"
                             :: "r"(saddr), "l"(fg + i) : "memory");
            }
        }
        asm volatile("cp.async.commit_group;\n" ::: "memory");
    }

    if (tid < Dn) sq[tid] = query[(size_t)b * Dn + tid];
    if (tid >= Dn && tid < Dn + Hn) sw2[tid - Dn] = W2[tid - Dn];
    __syncthreads();   // sq visible

    // ---- folded weights, packed so each ks is ONE LDS.128 per lane:
    // sB[((ks*8+gid)*4+tig)*4 + (nt*2+j)] = tf32(M[8ks+tig+4j][nt*8+gid])
    #pragma unroll
    for (int k = 0; k < (Dn * Hn) / NTHREADS; ++k) {   // 8 iters
        int i = tid + k * NTHREADS;
        int d = i >> 4;
        int h = i & 15;
        float wf = W1[(128 + d) * Hn + h];
        float wd = W1[(256 + d) * Hn + h];
        float wm = W1[(384 + d) * Hn + h];
        uint32_t r = f2tf32((wf - wd) + sq[d] * wm);
        int ks = d >> 3, tig = d & 3, j = (d >> 2) & 1;
        int nt = h >> 3, gid = h & 7;
        sB[(((ks * 8 + gid) * 4 + tig) * 4) + nt * 2 + j] = __uint_as_float(r);
    }

    // ---- c[h] = b1[h] + sum_d q[d]*(W1q + W1d)[d][h] ----
    {
        int h     = tid & 15;
        int chunk = tid >> 4;   // 16 chunks x 8 d
        float acc = 0.f;
        #pragma unroll
        for (int j = 0; j < 8; ++j) {
            int d = chunk * 8 + j;
            acc += sq[d] * (W1[d * Hn + h] + W1[(256 + d) * Hn + h]);
        }
        scpart[tid] = acc;
    }
    __syncthreads();
    if (tid < Hn) {
        float acc = b1[tid];
        #pragma unroll
        for (int k = 0; k < 16; ++k) acc += scpart[k * 16 + tid];
        sc[tid] = acc;
    }

    const int w    = tid >> 5;    // 8 warps
    const int lane = tid & 31;
    const int gid  = lane >> 2;
    const int tig  = lane & 3;

    // ---- scores via tf32 MMA: warp w -> local m-tile w (7 tiles cover t=0..111) ----
    #pragma unroll
    for (int stage = 0; stage < 2; ++stage) {
        if (stage == 0)
            asm volatile("cp.async.wait_group 1;\n" ::: "memory");
        else
            asm volatile("cp.async.wait_group 0;\n" ::: "memory");
        __syncthreads();

        bool active = (stage == 0) ? (w < 4) : (w >= 4 && w < 7);
        if (active) {
            const int t0 = w * 16 + gid;       // local rows
            const int t1 = t0 + 8;
            const int sw0 = t0 & 31, sw1 = t1 & 31;
            const float* f0 = sf + t0 * Dn + tig;
            const float* f1 = sf + t1 * Dn + tig;
            const float4* Bp = ((const float4*)sB) + gid * 4 + tig;

            const size_t mbase = (size_t)b * Tn + hb * Tl;
            int m0 = (t0 < Tl) ? mask[mbase + t0] : 0;
            int m1 = (t1 < Tl) ? mask[mbase + t1] : 0;

            float c0[4] = {0.f, 0.f, 0.f, 0.f};
            float c1[4] = {0.f, 0.f, 0.f, 0.f};
            #pragma unroll
            for (int ks = 0; ks < 16; ++ks) {
                uint32_t a[4];
                a[0] = __float_as_uint(f0[((2 * ks)     ^ sw0) << 2]);
                a[1] = __float_as_uint(f1[((2 * ks)     ^ sw1) << 2]);
                a[2] = __float_as_uint(f0[((2 * ks + 1) ^ sw0) << 2]);
                a[3] = __float_as_uint(f1[((2 * ks + 1) ^ sw1) << 2]);
                float4 bf = Bp[ks * 32];
                mma_tf32(c0, a, __float_as_uint(bf.x), __float_as_uint(bf.y));
                mma_tf32(c1, a, __float_as_uint(bf.z), __float_as_uint(bf.w));
            }

            float part0 = 0.f, part1 = 0.f;
            #pragma unroll
            for (int nt = 0; nt < 2; ++nt) {
                int h0 = nt * 8 + 2 * tig;
                float scA = sc[h0],   w2A = sw2[h0];
                float scB = sc[h0+1], w2B = sw2[h0+1];
                const float* cc = nt ? c1 : c0;
                part0 += __fdividef(w2A, 1.0f + __expf(-(cc[0] + scA)));
                part0 += __fdividef(w2B, 1.0f + __expf(-(cc[1] + scB)));
                part1 += __fdividef(w2A, 1.0f + __expf(-(cc[2] + scA)));
                part1 += __fdividef(w2B, 1.0f + __expf(-(cc[3] + scB)));
            }
            part0 += __shfl_xor_sync(0xffffffffu, part0, 1);
            part0 += __shfl_xor_sync(0xffffffffu, part0, 2);
            part1 += __shfl_xor_sync(0xffffffffu, part1, 1);
            part1 += __shfl_xor_sync(0xffffffffu, part1, 2);

            float e0 = (t0 < Tl && m0) ? __expf(b2v + part0) : 0.f;
            float e1 = (t1 < Tl && m1) ? __expf(b2v + part1) : 0.f;
            if (tig == 0) {
                if (t0 < Tl) sscore[t0] = e0;
                if (t1 < Tl) sscore[t1] = e1;
            }
            float es = e0 + e1;            // tig-uniform; reduce over gid
            es += __shfl_xor_sync(0xffffffffu, es, 4);
            es += __shfl_xor_sync(0xffffffffu, es, 8);
            es += __shfl_xor_sync(0xffffffffu, es, 16);
            if (lane == 0) sred[w] = es;
        }
    }
    __syncthreads();   // sscore + sred[0..6] ready; sB dead (spart8 aliases)

    if (tid == 0) {
        float ssum = 0.f;
        #pragma unroll
        for (int k = 0; k < 7; ++k) ssum += sred[k];
        atomicAdd(&g_sum[b], ssum);       // red.add, fire-and-forget
    }

    // ---- local weighted sum: slice w handles local t = w + 8*i ----
    {
        const int dg = lane;
        // t steps by 8: swizzle group cycles over {w, w+8, w+16, w+24}
        const float4* base = (const float4*)sf;
        long p0 = (long)(w        * 32 + (dg ^  w      ));
        long p1 = (long)((w + 8)  * 32 + (dg ^ (w + 8) ));
        long p2 = (long)((w + 16) * 32 + (dg ^ (w + 16)));
        long p3 = (long)((w + 24) * 32 + (dg ^ (w + 24)));
        float4 acc = make_float4(0.f, 0.f, 0.f, 0.f);
        #pragma unroll
        for (int m = 0; m < 3; ++m) {
            int tb = w + 32 * m;
            float a0 = sscore[tb];
            float4 f0v = base[p0 + 1024 * m];
            acc.x += a0 * f0v.x; acc.y += a0 * f0v.y; acc.z += a0 * f0v.z; acc.w += a0 * f0v.w;
            float a1 = sscore[tb + 8];
            float4 f1v = base[p1 + 1024 * m];
            acc.x += a1 * f1v.x; acc.y += a1 * f1v.y; acc.z += a1 * f1v.z; acc.w += a1 * f1v.w;
            float a2 = sscore[tb + 16];
            float4 f2v = base[p2 + 1024 * m];
            acc.x += a2 * f2v.x; acc.y += a2 * f2v.y; acc.z += a2 * f2v.z; acc.w += a2 * f2v.w;
            float a3 = sscore[tb + 24];
            float4 f3v = base[p3 + 1024 * m];
            acc.x += a3 * f3v.x; acc.y += a3 * f3v.y; acc.z += a3 * f3v.z; acc.w += a3 * f3v.w;
        }
        if (w < 4) {   // t = w + 96
            float a0 = sscore[w + 96];
            float4 f0v = base[p0 + 1024 * 3];
            acc.x += a0 * f0v.x; acc.y += a0 * f0v.y; acc.z += a0 * f0v.z; acc.w += a0 * f0v.w;
        }
        ((float4*)spart8)[w * 32 + dg] = acc;
    }
    __syncthreads();

    // ---- reduce 8 slices, add to global partials ----
    if (tid < Dn) {
        float p = 0.f;
        #pragma unroll
        for (int s = 0; s < 8; ++s) p += spart8[s * Dn + tid];
        atomicAdd(&g_part[b][tid], p);
    }
    __threadfence();
    __syncthreads();

    if (tid == 0) {
        unsigned old = atomicAdd(&g_cnt[b], 1u);
        sred[15] = __uint_as_float(old);
    }
    __syncthreads();

    if (__float_as_uint(sred[15]) == 1u) {   // second arriver finalizes (CTA-uniform branch)
        __threadfence();
        float stot = __ldcg(&g_sum[b]);
        float p = 0.f;
        if (tid < Dn) p = __ldcg(&g_part[b][tid]);
        __syncthreads();                     // ALL reads complete before any reset
        if (tid < Dn) {
            out[(size_t)b * Dn + tid] = p / stot;
            g_part[b][tid] = 0.f;            // reset scratch for next replay
        }
        if (tid == 0) {
            g_sum[b] = 0.f;
            g_cnt[b] = 0u;
        }
    }
}

extern "C" void kernel_launch(void* const* d_in, const int* in_sizes, int n_in,
                              void* d_out, int out_size) {
    const float* query = (const float*)d_in[0];
    const float* facts = (const float*)d_in[1];
    const int*   mask  = (const int*)d_in[2];
    const float* W1    = (const float*)d_in[3];
    const float* b1    = (const float*)d_in[4];
    const float* W2    = (const float*)d_in[5];
    const float* b2    = (const float*)d_in[6];
    float*       out   = (float*)d_out;

    int B = in_sizes[0] / Dn;   // 4096
    size_t smem = SMEM_FLOATS * sizeof(float);   // 61536 B
    cudaFuncSetAttribute(din_kernel, cudaFuncAttributeMaxDynamicSharedMemorySize, (int)smem);
    din_kernel<<<B * 2, NTHREADS, smem>>>(query, facts, mask, W1, b1, W2, b2, out);
}

// round 8
// speedup vs baseline: 1.1239x; 1.1239x over previous
#include <cuda_runtime.h>
#include <cstdint>
#include <cstddef>

#define Bn 4096
#define Tn 200
#define Dn 128
#define Hn 16
#define NTHREADS 512
#define GRID 148

// smem floats: sf0 25600 | sf1 25600 | sB 2048 (aliased by spart16) | sq 128
//              sc 16 | sw2 16 | sscore 200 | sred 16 | scpart 256 = 53880 floats = 215520 B
#define SMEM_FLOATS (25600*2 + 2048 + 128 + 16 + 16 + 200 + 16 + 256)

__device__ __forceinline__ uint32_t f2tf32(float x) {
    uint32_t u;
    asm("cvt.rna.tf32.f32 %0, %1;" : "=r"(u) : "f"(x));
    return u;
}

__device__ __forceinline__ void mma_tf32(float c[4], const uint32_t a[4],
                                         uint32_t b0, uint32_t b1) {
    asm volatile(
        "mma.sync.aligned.m16n8k8.row.col.f32.tf32.tf32.f32 "
        "{%0,%1,%2,%3}, {%4,%5,%6,%7}, {%8,%9}, {%0,%1,%2,%3};"
        : "+f"(c[0]), "+f"(c[1]), "+f"(c[2]), "+f"(c[3])
        : "r"(a[0]), "r"(a[1]), "r"(a[2]), "r"(a[3]), "r"(b0), "r"(b1));
}

#define PREFETCH_TILE(dstbase, srcp)                                            \
    {                                                                           \
        const float4* fg_ = (const float4*)(srcp);                              \
        _Pragma("unroll")                                                       \
        for (int k_ = 0; k_ < 13; ++k_) {                                       \
            int i_ = tid + k_ * NTHREADS;                                       \
            if (i_ < 6400) {                                                    \
                int t_  = i_ >> 5;                                              \
                int dg_ = i_ & 31;                                              \
                float4* dst_ = ((float4*)(dstbase)) + (t_ * 32 + (dg_ ^ (t_ & 31))); \
                unsigned sa_ = (unsigned)__cvta_generic_to_shared(dst_);        \
                asm volatile("cp.async.cg.shared.global [%0], [%1], 16;\n"     \
                             :: "r"(sa_), "l"(fg_ + i_) : "memory");            \
            }                                                                   \
        }                                                                       \
    }

__global__ void __launch_bounds__(NTHREADS, 1) din_kernel(
    const float* __restrict__ query,
    const float* __restrict__ facts,
    const int* __restrict__ mask,
    const float* __restrict__ W1,
    const float* __restrict__ b1,
    const float* __restrict__ W2,
    const float* __restrict__ b2,
    float* __restrict__ out)
{
    extern __shared__ float smem[];
    float* sf0    = smem;
    float* sf1    = smem + 25600;
    float* sB     = smem + 51200;         // 2048; aliased by spart16 after scores
    float* sq     = sB + 2048;            // 128
    float* sc     = sq + Dn;              // 16
    float* sw2    = sc + Hn;              // 16
    float* sscore = sw2 + Hn;             // 200 (exp(score))
    float* sred   = sscore + Tn;          // 16
    float* scpart = sred + 16;            // 256
    float* spart16 = sB;                  // alias: 16 x 128 wsum partials

    const int tid  = threadIdx.x;
    const int w    = tid >> 5;    // 16 warps
    const int lane = tid & 31;
    const int gid  = lane >> 2;
    const int tig  = lane & 3;
    const float b2v = b2[0];

    if (tid < Hn) sw2[tid] = W2[tid];

    // prologue: prefetch first tile into sf0
    PREFETCH_TILE(sf0, facts + (size_t)blockIdx.x * (Tn * Dn));
    asm volatile("cp.async.commit_group;\n" ::: "memory");

    int cur = 0;
    for (int b = blockIdx.x; b < Bn; b += GRID, cur ^= 1) {
        float* sfc = cur ? sf1 : sf0;
        float* sfn = cur ? sf0 : sf1;

        // ---- prefetch next batch tile (own commit group; empty group if none) ----
        int bnext = b + GRID;
        if (bnext < Bn) PREFETCH_TILE(sfn, facts + (size_t)bnext * (Tn * Dn));
        asm volatile("cp.async.commit_group;\n" ::: "memory");

        if (tid < Dn) sq[tid] = query[(size_t)b * Dn + tid];
        __syncthreads();   // sq visible; prev iter fully done (loop-end barrier)

        // ---- folded weights, packed so each ks is ONE LDS.128 per lane ----
        #pragma unroll
        for (int k = 0; k < (Dn * Hn) / NTHREADS; ++k) {   // 4 iters
            int i = tid + k * NTHREADS;
            int d = i >> 4;
            int h = i & 15;
            float wf = W1[(128 + d) * Hn + h];
            float wd = W1[(256 + d) * Hn + h];
            float wm = W1[(384 + d) * Hn + h];
            uint32_t r = f2tf32((wf - wd) + sq[d] * wm);
            int ks = d >> 3, tg = d & 3, j = (d >> 2) & 1;
            int nt = h >> 3, gg = h & 7;
            sB[(((ks * 8 + gg) * 4 + tg) * 4) + nt * 2 + j] = __uint_as_float(r);
        }
        // ---- c[h] partials ----
        if (tid < 256) {
            int h     = tid & 15;
            int chunk = tid >> 4;
            float acc = 0.f;
            #pragma unroll
            for (int j = 0; j < 8; ++j) {
                int d = chunk * 8 + j;
                acc += sq[d] * (W1[d * Hn + h] + W1[(256 + d) * Hn + h]);
            }
            scpart[tid] = acc;
        }
        __syncthreads();
        if (tid < Hn) {
            float acc = b1[tid];
            #pragma unroll
            for (int k = 0; k < 16; ++k) acc += scpart[k * 16 + tid];
            sc[tid] = acc;
        }
        asm volatile("cp.async.wait_group 1;\n" ::: "memory");   // current tile resident
        __syncthreads();

        // ---- scores via tf32 MMA: warp w -> m-tile w (13 tiles cover t=0..207) ----
        if (w < 13) {
            const int t0 = w * 16 + gid;
            const int t1 = t0 + 8;
            const int sw0 = t0 & 31, sw1 = t1 & 31;
            const float* f0 = sfc + t0 * Dn + tig;
            const float* f1 = sfc + t1 * Dn + tig;
            const float4* Bp = ((const float4*)sB) + gid * 4 + tig;

            int m0 = mask[(size_t)b * Tn + t0];                       // t0 <= 199
            int m1 = (t1 < Tn) ? mask[(size_t)b * Tn + t1] : 0;

            float c0a[4] = {0,0,0,0}, c0b[4] = {0,0,0,0};
            float c1a[4] = {0,0,0,0}, c1b[4] = {0,0,0,0};
            #pragma unroll
            for (int ks = 0; ks < 16; ks += 2) {
                uint32_t a[4];
                a[0] = __float_as_uint(f0[((2 * ks)     ^ sw0) << 2]);
                a[1] = __float_as_uint(f1[((2 * ks)     ^ sw1) << 2]);
                a[2] = __float_as_uint(f0[((2 * ks + 1) ^ sw0) << 2]);
                a[3] = __float_as_uint(f1[((2 * ks + 1) ^ sw1) << 2]);
                float4 bf = Bp[ks * 32];
                mma_tf32(c0a, a, __float_as_uint(bf.x), __float_as_uint(bf.y));
                mma_tf32(c1a, a, __float_as_uint(bf.z), __float_as_uint(bf.w));
                uint32_t a2[4];
                a2[0] = __float_as_uint(f0[((2 * ks + 2) ^ sw0) << 2]);
                a2[1] = __float_as_uint(f1[((2 * ks + 2) ^ sw1) << 2]);
                a2[2] = __float_as_uint(f0[((2 * ks + 3) ^ sw0) << 2]);
                a2[3] = __float_as_uint(f1[((2 * ks + 3) ^ sw1) << 2]);
                float4 bg = Bp[(ks + 1) * 32];
                mma_tf32(c0b, a2, __float_as_uint(bg.x), __float_as_uint(bg.y));
                mma_tf32(c1b, a2, __float_as_uint(bg.z), __float_as_uint(bg.w));
            }
            float c0[4], c1[4];
            #pragma unroll
            for (int i = 0; i < 4; ++i) { c0[i] = c0a[i] + c0b[i]; c1[i] = c1a[i] + c1b[i]; }

            float part0 = 0.f, part1 = 0.f;
            #pragma unroll
            for (int nt = 0; nt < 2; ++nt) {
                int h0 = nt * 8 + 2 * tig;
                float scA = sc[h0],   w2A = sw2[h0];
                float scB = sc[h0+1], w2B = sw2[h0+1];
                const float* cc = nt ? c1 : c0;
                part0 += __fdividef(w2A, 1.0f + __expf(-(cc[0] + scA)));
                part0 += __fdividef(w2B, 1.0f + __expf(-(cc[1] + scB)));
                part1 += __fdividef(w2A, 1.0f + __expf(-(cc[2] + scA)));
                part1 += __fdividef(w2B, 1.0f + __expf(-(cc[3] + scB)));
            }
            part0 += __shfl_xor_sync(0xffffffffu, part0, 1);
            part0 += __shfl_xor_sync(0xffffffffu, part0, 2);
            part1 += __shfl_xor_sync(0xffffffffu, part1, 1);
            part1 += __shfl_xor_sync(0xffffffffu, part1, 2);

            float e0 = m0 ? __expf(b2v + part0) : 0.f;
            float e1 = (t1 < Tn && m1) ? __expf(b2v + part1) : 0.f;
            if (tig == 0) {
                sscore[t0] = e0;
                if (t1 < Tn) sscore[t1] = e1;
            }
            float es = e0 + e1;
            es += __shfl_xor_sync(0xffffffffu, es, 4);
            es += __shfl_xor_sync(0xffffffffu, es, 8);
            es += __shfl_xor_sync(0xffffffffu, es, 16);
            if (lane == 0) sred[w] = es;
        }
        __syncthreads();   // sscore + sred ready; sB dead -> spart16

        if (tid == 0) {
            float ssum = 0.f;
            #pragma unroll
            for (int k = 0; k < 13; ++k) ssum += sred[k];
            sred[15] = 1.0f / ssum;
        }

        // ---- weighted sum: slice w handles t = w + 16*i (dual streams) ----
        {
            const int dg = lane;
            const float4* p0 = ((const float4*)sfc) + w * 32 + (dg ^ w);
            const float4* p1 = ((const float4*)sfc) + (w + 16) * 32 + (dg ^ (w + 16));
            float4 accA = make_float4(0,0,0,0), accB = make_float4(0,0,0,0);
            #pragma unroll
            for (int i = 0; i < 6; ++i) {
                float a0 = sscore[w + 32 * i];
                float4 f4 = p0[i * 1024];
                accA.x += a0 * f4.x; accA.y += a0 * f4.y; accA.z += a0 * f4.z; accA.w += a0 * f4.w;
                float a1 = sscore[w + 16 + 32 * i];
                float4 g4 = p1[i * 1024];
                accB.x += a1 * g4.x; accB.y += a1 * g4.y; accB.z += a1 * g4.z; accB.w += a1 * g4.w;
            }
            if (w < 8) {
                float a0 = sscore[w + 192];
                float4 f4 = p0[6 * 1024];
                accA.x += a0 * f4.x; accA.y += a0 * f4.y; accA.z += a0 * f4.z; accA.w += a0 * f4.w;
            }
            accA.x += accB.x; accA.y += accB.y; accA.z += accB.z; accA.w += accB.w;
            ((float4*)spart16)[w * 32 + dg] = accA;
        }
        __syncthreads();

        if (tid < Dn) {
            const float inv = sred[15];
            float acc = 0.f;
            #pragma unroll
            for (int s = 0; s < 16; ++s) acc += spart16[s * Dn + tid];
            out[(size_t)b * Dn + tid] = acc * inv;
        }
        __syncthreads();   // spart16/sscore free before next iter writes
    }
}

extern "C" void kernel_launch(void* const* d_in, const int* in_sizes, int n_in,
                              void* d_out, int out_size) {
    const float* query = (const float*)d_in[0];
    const float* facts = (const float*)d_in[1];
    const int*   mask  = (const int*)d_in[2];
    const float* W1    = (const float*)d_in[3];
    const float* b1    = (const float*)d_in[4];
    const float* W2    = (const float*)d_in[5];
    const float* b2    = (const float*)d_in[6];
    float*       out   = (float*)d_out;

    size_t smem = SMEM_FLOATS * sizeof(float);   // 215520 B
    cudaFuncSetAttribute(din_kernel, cudaFuncAttributeMaxDynamicSharedMemorySize, (int)smem);
    din_kernel<<<GRID, NTHREADS, smem>>>(query, facts, mask, W1, b1, W2, b2, out);
}

// round 9
// speedup vs baseline: 1.1550x; 1.0277x over previous
#include <cuda_runtime.h>
#include <cuda.h>
#include <cstdint>
#include <cstddef>
#include <cstring>

#define Bn 4096
#define Tn 200
#define Dn 128
#define Hn 16
#define NTHREADS 512
#define PANELB 25600            // bytes per k-panel (200 rows x 128 B)

// float offsets within aligned smem
#define OF_SF     0             // 4 panels = 25600 floats (102400 B)
#define OF_SB     25600         // 2048 (aliased by spart16 later)
#define OF_SQ     27648         // 128
#define OF_SC     27776         // 16
#define OF_SW2    27792         // 16
#define OF_SSC    27808         // 200
#define OF_SRED   28008         // 16
#define OF_SCP    28024         // 256
#define OF_MBAR   28280         // 2 floats (8B mbarrier)
#define SMEM_FLOATS 28284
#define SMEM_BYTES (SMEM_FLOATS * 4 + 1024)   // +1024 for manual alignment

__device__ __forceinline__ uint32_t f2tf32(float x) {
    uint32_t u;
    asm("cvt.rna.tf32.f32 %0, %1;" : "=r"(u) : "f"(x));
    return u;
}

__device__ __forceinline__ void mma_tf32(float c[4], const uint32_t a[4],
                                         uint32_t b0, uint32_t b1) {
    asm volatile(
        "mma.sync.aligned.m16n8k8.row.col.f32.tf32.tf32.f32 "
        "{%0,%1,%2,%3}, {%4,%5,%6,%7}, {%8,%9}, {%0,%1,%2,%3};"
        : "+f"(c[0]), "+f"(c[1]), "+f"(c[2]), "+f"(c[3])
        : "r"(a[0]), "r"(a[1]), "r"(a[2]), "r"(a[3]), "r"(b0), "r"(b1));
}

__device__ __forceinline__ void mbar_wait0(uint32_t mbar) {
    asm volatile(
        "{\n\t.reg .pred P;\n\t"
        "WLP_%=:\n\t"
        "mbarrier.try_wait.parity.acquire.cta.shared::cta.b64 P, [%0], 0, 0x989680;\n\t"
        "@P bra.uni WDN_%=;\n\t"
        "bra.uni WLP_%=;\n\t"
        "WDN_%=:\n\t}"
        :: "r"(mbar) : "memory");
}

__global__ void __launch_bounds__(NTHREADS, 2) din_kernel(
    const float* __restrict__ query,
    const float* __restrict__ facts,
    const int* __restrict__ mask,
    const float* __restrict__ W1,
    const float* __restrict__ b1,
    const float* __restrict__ W2,
    const float* __restrict__ b2,
    float* __restrict__ out,
    const __grid_constant__ CUtensorMap tmap,
    const int use_tma)
{
    extern __shared__ float smem_raw[];
    float* smem = (float*)(((uintptr_t)smem_raw + 1023) & ~(uintptr_t)1023);
    char*  sfb     = (char*)smem;          // 4 SW128 panels at byte 0
    float* sB      = smem + OF_SB;
    float* sq      = smem + OF_SQ;
    float* sc      = smem + OF_SC;
    float* sw2     = smem + OF_SW2;
    float* sscore  = smem + OF_SSC;
    float* sred    = smem + OF_SRED;
    float* scpart  = smem + OF_SCP;
    float* spart16 = sB;                   // alias after MMA phase

    const int b    = blockIdx.x;
    const int tid  = threadIdx.x;
    const int w    = tid >> 5;             // 16 warps
    const int lane = tid & 31;
    const int gid  = lane >> 2;
    const int tig  = lane & 3;
    const float b2v = b2[0];

    const uint32_t smem_u32 = (uint32_t)__cvta_generic_to_shared(smem);
    const uint32_t mbar_u32 = smem_u32 + OF_MBAR * 4;

    // ---- facts tile load: TMA (4 SW128 panels) or cp.async fallback ----
    if (use_tma) {
        if (tid == 0) {
            asm volatile("mbarrier.init.shared.b64 [%0], 1;" :: "r"(mbar_u32) : "memory");
            asm volatile("fence.proxy.async.shared::cta;" ::: "memory");
            asm volatile("mbarrier.arrive.expect_tx.shared.b64 _, [%0], %1;"
                         :: "r"(mbar_u32), "r"(102400u) : "memory");
            #pragma unroll
            for (int p = 0; p < 4; ++p) {
                asm volatile(
                    "cp.async.bulk.tensor.2d.shared::cta.global.tile.mbarrier::complete_tx::bytes "
                    "[%0], [%1, {%2, %3}], [%4];"
                    :: "r"(smem_u32 + p * PANELB), "l"(&tmap),
                       "r"(p * 32), "r"(b * Tn), "r"(mbar_u32)
                    : "memory");
            }
        }
    } else {
        const float4* fg = (const float4*)(facts + (size_t)b * (Tn * Dn));
        #pragma unroll
        for (int k = 0; k < 13; ++k) {
            int i = tid + k * NTHREADS;
            if (i < 6400) {
                int t = i >> 5, u = i & 31;
                uint32_t dst = smem_u32 + (u >> 3) * PANELB + t * 128
                             + (((u & 7) * 16) ^ ((t & 7) << 4));
                asm volatile("cp.async.cg.shared.global [%0], [%1], 16;\n"
                             :: "r"(dst), "l"(fg + i) : "memory");
            }
        }
        asm volatile("cp.async.commit_group;\n" ::: "memory");
    }

    if (tid < Dn) sq[tid] = query[(size_t)b * Dn + tid];
    if (tid >= Dn && tid < Dn + Hn) sw2[tid - Dn] = W2[tid - Dn];
    __syncthreads();   // sq visible; mbar init ordered before any wait

    // ---- folded weights, packed so each ks is ONE LDS.128 per lane ----
    #pragma unroll
    for (int k = 0; k < (Dn * Hn) / NTHREADS; ++k) {   // 4 iters
        int i = tid + k * NTHREADS;
        int d = i >> 4;
        int h = i & 15;
        float wf = W1[(128 + d) * Hn + h];
        float wd = W1[(256 + d) * Hn + h];
        float wm = W1[(384 + d) * Hn + h];
        uint32_t r = f2tf32((wf - wd) + sq[d] * wm);
        int ks = d >> 3, tg = d & 3, j = (d >> 2) & 1;
        int nt = h >> 3, gg = h & 7;
        sB[(((ks * 8 + gg) * 4 + tg) * 4) + nt * 2 + j] = __uint_as_float(r);
    }
    // ---- c[h] partials ----
    if (tid < 256) {
        int h     = tid & 15;
        int chunk = tid >> 4;
        float acc = 0.f;
        #pragma unroll
        for (int j = 0; j < 8; ++j) {
            int d = chunk * 8 + j;
            acc += sq[d] * (W1[d * Hn + h] + W1[(256 + d) * Hn + h]);
        }
        scpart[tid] = acc;
    }
    __syncthreads();
    if (tid < Hn) {
        float acc = b1[tid];
        #pragma unroll
        for (int k = 0; k < 16; ++k) acc += scpart[k * 16 + tid];
        sc[tid] = acc;
    }

    // ---- wait for facts tile ----
    if (use_tma) {
        mbar_wait0(mbar_u32);
    } else {
        asm volatile("cp.async.wait_group 0;\n" ::: "memory");
    }
    __syncthreads();   // tile + sB + sc all visible

    // ---- scores via tf32 MMA: warp w -> m-tile w (13 tiles cover t=0..207) ----
    if (w < 13) {
        const int t0 = w * 16 + gid;
        const int t1 = t0 + 8;
        const int var0 = (t0 & 7) << 4, var1 = (t1 & 7) << 4;
        const int row0 = t0 * 128,      row1 = t1 * 128;
        const int tig4 = tig * 4;
        const float4* Bp = ((const float4*)sB) + gid * 4 + tig;

        int m0 = mask[(size_t)b * Tn + t0];
        int m1 = (t1 < Tn) ? mask[(size_t)b * Tn + t1] : 0;

        float c0a[4] = {0,0,0,0}, c0b[4] = {0,0,0,0};
        float c1a[4] = {0,0,0,0}, c1b[4] = {0,0,0,0};
        #pragma unroll
        for (int ks = 0; ks < 16; ks += 2) {
            int pb = (ks >> 2) * PANELB;
            int c  = (ks & 3) * 32 + tig4;
            uint32_t a[4];
            a[0] = __float_as_uint(*(const float*)(sfb + pb + row0 + ( c       ^ var0)));
            a[1] = __float_as_uint(*(const float*)(sfb + pb + row1 + ( c       ^ var1)));
            a[2] = __float_as_uint(*(const float*)(sfb + pb + row0 + ((c + 16) ^ var0)));
            a[3] = __float_as_uint(*(const float*)(sfb + pb + row1 + ((c + 16) ^ var1)));
            float4 bf = Bp[ks * 32];
            mma_tf32(c0a, a, __float_as_uint(bf.x), __float_as_uint(bf.y));
            mma_tf32(c1a, a, __float_as_uint(bf.z), __float_as_uint(bf.w));
            int pb2 = ((ks + 1) >> 2) * PANELB;
            int c2  = ((ks + 1) & 3) * 32 + tig4;
            uint32_t a2[4];
            a2[0] = __float_as_uint(*(const float*)(sfb + pb2 + row0 + ( c2       ^ var0)));
            a2[1] = __float_as_uint(*(const float*)(sfb + pb2 + row1 + ( c2       ^ var1)));
            a2[2] = __float_as_uint(*(const float*)(sfb + pb2 + row0 + ((c2 + 16) ^ var0)));
            a2[3] = __float_as_uint(*(const float*)(sfb + pb2 + row1 + ((c2 + 16) ^ var1)));
            float4 bg = Bp[(ks + 1) * 32];
            mma_tf32(c0b, a2, __float_as_uint(bg.x), __float_as_uint(bg.y));
            mma_tf32(c1b, a2, __float_as_uint(bg.z), __float_as_uint(bg.w));
        }
        float c0[4], c1[4];
        #pragma unroll
        for (int i = 0; i < 4; ++i) { c0[i] = c0a[i] + c0b[i]; c1[i] = c1a[i] + c1b[i]; }

        float part0 = 0.f, part1 = 0.f;
        #pragma unroll
        for (int nt = 0; nt < 2; ++nt) {
            int h0 = nt * 8 + 2 * tig;
            float scA = sc[h0],   w2A = sw2[h0];
            float scB = sc[h0+1], w2B = sw2[h0+1];
            const float* cc = nt ? c1 : c0;
            part0 += __fdividef(w2A, 1.0f + __expf(-(cc[0] + scA)));
            part0 += __fdividef(w2B, 1.0f + __expf(-(cc[1] + scB)));
            part1 += __fdividef(w2A, 1.0f + __expf(-(cc[2] + scA)));
            part1 += __fdividef(w2B, 1.0f + __expf(-(cc[3] + scB)));
        }
        part0 += __shfl_xor_sync(0xffffffffu, part0, 1);
        part0 += __shfl_xor_sync(0xffffffffu, part0, 2);
        part1 += __shfl_xor_sync(0xffffffffu, part1, 1);
        part1 += __shfl_xor_sync(0xffffffffu, part1, 2);

        float e0 = m0 ? __expf(b2v + part0) : 0.f;
        float e1 = (t1 < Tn && m1) ? __expf(b2v + part1) : 0.f;
        if (tig == 0) {
            sscore[t0] = e0;
            if (t1 < Tn) sscore[t1] = e1;
        }
        float es = e0 + e1;
        es += __shfl_xor_sync(0xffffffffu, es, 4);
        es += __shfl_xor_sync(0xffffffffu, es, 8);
        es += __shfl_xor_sync(0xffffffffu, es, 16);
        if (lane == 0) sred[w] = es;
    }
    __syncthreads();   // sscore + sred ready; sB dead -> spart16

    if (tid == 0) {
        float ssum = 0.f;
        #pragma unroll
        for (int k = 0; k < 13; ++k) ssum += sred[k];
        sred[15] = 1.0f / ssum;
    }

    // ---- weighted sum from GLOBAL (L2-hot, coalesced): warp w -> t = w + 16i ----
    {
        const float4* fb = (const float4*)(facts + (size_t)b * (Tn * Dn));
        float4 acc = make_float4(0.f, 0.f, 0.f, 0.f);
        const int nit = (w < 8) ? 13 : 12;
        #pragma unroll
        for (int i = 0; i < 13; ++i) {
            if (i < nit) {
                int t = w + 16 * i;
                float a0 = sscore[t];
                float4 f4 = fb[t * 32 + lane];
                acc.x += a0 * f4.x; acc.y += a0 * f4.y;
                acc.z += a0 * f4.z; acc.w += a0 * f4.w;
            }
        }
        ((float4*)spart16)[w * 32 + lane] = acc;
    }
    __syncthreads();

    if (tid < Dn) {
        const float inv = sred[15];
        float acc = 0.f;
        #pragma unroll
        for (int s = 0; s < 16; ++s) acc += spart16[s * Dn + tid];
        out[(size_t)b * Dn + tid] = acc * inv;
    }
}

typedef CUresult (*PFN_encodeTiled_t)(
    CUtensorMap*, CUtensorMapDataType, cuuint32_t, void*,
    const cuuint64_t*, const cuuint64_t*, const cuuint32_t*, const cuuint32_t*,
    CUtensorMapInterleave, CUtensorMapSwizzle, CUtensorMapL2promotion,
    CUtensorMapFloatOOBfill);

extern "C" void kernel_launch(void* const* d_in, const int* in_sizes, int n_in,
                              void* d_out, int out_size) {
    const float* query = (const float*)d_in[0];
    const float* facts = (const float*)d_in[1];
    const int*   mask  = (const int*)d_in[2];
    const float* W1    = (const float*)d_in[3];
    const float* b1    = (const float*)d_in[4];
    const float* W2    = (const float*)d_in[5];
    const float* b2    = (const float*)d_in[6];
    float*       out   = (float*)d_out;

    int B = in_sizes[0] / Dn;   // 4096

    CUtensorMap tmap;
    memset(&tmap, 0, sizeof(tmap));
    int use_tma = 0;

    PFN_encodeTiled_t fn = nullptr;
    cudaDriverEntryPointQueryResult qr = cudaDriverEntryPointSymbolNotFound;
#if CUDART_VERSION >= 12050
    cudaGetDriverEntryPointByVersion("cuTensorMapEncodeTiled", (void**)&fn, 12000,
                                     cudaEnableDefault, &qr);
#else
    cudaGetDriverEntryPoint("cuTensorMapEncodeTiled", (void**)&fn,
                            cudaEnableDefault, &qr);
#endif
    if (qr == cudaDriverEntryPointSuccess && fn) {
        cuuint64_t gdim[2]    = {(cuuint64_t)Dn, (cuuint64_t)B * Tn};
        cuuint64_t gstride[1] = {(cuuint64_t)Dn * 4};
        cuuint32_t box[2]     = {32, 200};
        cuuint32_t estride[2] = {1, 1};
        CUresult r = fn(&tmap, CU_TENSOR_MAP_DATA_TYPE_FLOAT32, 2, (void*)facts,
                        gdim, gstride, box, estride,
                        CU_TENSOR_MAP_INTERLEAVE_NONE, CU_TENSOR_MAP_SWIZZLE_128B,
                        CU_TENSOR_MAP_L2_PROMOTION_L2_128B,
                        CU_TENSOR_MAP_FLOAT_OOB_FILL_NONE);
        if (r == CUDA_SUCCESS) use_tma = 1;
    }

    cudaFuncSetAttribute(din_kernel, cudaFuncAttributeMaxDynamicSharedMemorySize,
                         SMEM_BYTES);
    din_kernel<<<B, NTHREADS, SMEM_BYTES>>>(query, facts, mask, W1, b1, W2, b2,
                                            out, tmap, use_tma);
}